// round 15
// baseline (speedup 1.0000x reference)
#include <cuda_runtime.h>
#include <math.h>
#include <string.h>

#define HDIM   256
#define NCELL  32
#define DTH    31
#define EPSF   1e-7f
#define TINYF  1e-10f
#define GTAB   1024                  // table cells; nodes = GTAB+1
#define NGRP   33                    // row groups of 32 (covers GTAB+1 rows)

// ---------------- device scratch (no cudaMalloc allowed) ----------------
__device__ float g_Atab[(GTAB + 64) * 64];   // A table rows (+pad)

struct BParam { float B[DTH * 64]; };        // 7936 B kernel param

// ---------------- dynamic shared-memory overlay for kAll ----------------
struct SmemAll {
    float us[HDIM], cs[HDIM], xs[32];
    union {
        struct { float up[4][HDIM]; float cp[4][HDIM]; } s0;   // fold partials
        struct { float As[16][36];  float Bs[16][256]; } s1;   // GEMM tiles
        struct { float Ts[32][33];  float Bb[DTH][64]; } s34;  // projection
    } u;
    float H2t[32][256];              // H2 tile [i][k]
};

// ============================================================================
// Host: numpy SVD null-space basis B = Vt[33:].T via Householder LQ
// (dgesdd Path 4t: dgelqf + dorglq). Input-independent -> host fp64.
// ============================================================================
static void compute_basis_host(float* Bout /* [DTH][64] */)
{
    static double L[33][64];
    static double Bm[DTH][64];
    static double tau[33];
    memset(L, 0, sizeof(L));
    memset(Bm, 0, sizeof(Bm));

    for (int i = 1; i < NCELL; i++) {
        double xi = (double)i / (double)NCELL;
        L[i - 1][2 * (i - 1)]     = xi;
        L[i - 1][2 * (i - 1) + 1] = 1.0;
        L[i - 1][2 * i]           = -xi;
        L[i - 1][2 * i + 1]       = -1.0;
    }
    L[NCELL - 1][1]               = 1.0;
    L[NCELL][2 * (NCELL - 1)]     = 1.0;
    L[NCELL][2 * (NCELL - 1) + 1] = 1.0;

    for (int i = 0; i < 33; i++) {
        double xn2 = 0.0;
        for (int j = i + 1; j < 64; j++) xn2 += L[i][j] * L[i][j];
        if (xn2 == 0.0) { tau[i] = 0.0; continue; }
        double alpha = L[i][i];
        double beta = sqrt(alpha * alpha + xn2);
        beta = (alpha >= 0.0) ? -beta : beta;
        tau[i] = (beta - alpha) / beta;
        double sc = 1.0 / (alpha - beta);
        for (int j = i + 1; j < 64; j++) L[i][j] *= sc;
        L[i][i] = beta;
        for (int r = i + 1; r < 33; r++) {
            double w = L[r][i];
            for (int j = i + 1; j < 64; j++) w += L[r][j] * L[i][j];
            w *= tau[i];
            L[r][i] -= w;
            for (int j = i + 1; j < 64; j++) L[r][j] -= w * L[i][j];
        }
    }
    for (int r = 0; r < DTH; r++) Bm[r][33 + r] = 1.0;
    for (int i = 32; i >= 0; i--) {
        if (tau[i] == 0.0) continue;
        for (int r = 0; r < DTH; r++) {
            double w = Bm[r][i];
            for (int j = i + 1; j < 64; j++) w += Bm[r][j] * L[i][j];
            w *= tau[i];
            Bm[r][i] -= w;
            for (int j = i + 1; j < 64; j++) Bm[r][j] -= w * L[i][j];
        }
    }
    for (int d = 0; d < DTH; d++)
        for (int j = 0; j < 64; j++)
            Bout[d * 64 + j] = (float)Bm[d][j];
}

// ============================================================================
// kAll: the ENTIRE table pipeline, one self-sufficient block per 32 rows.
//   S0: u = w0@w1, c = b0@w1 + b1  (in-block, 4 fixed-order k-chunks)
//   S1: H2 = relu( relu(x*u+c) @ w2 + b2 )   (32x256 GEMM -> smem)
//   S2: T  = H2 @ w3 + b3                    (32x31)
//   S3: A  = T @ B^T                         -> g_Atab
// No cross-block dependencies -> no spin sync (R13 failure mode avoided).
// 33 blocks x 1024 threads; dynamic smem ~53 KB.
// ============================================================================
__global__ void __launch_bounds__(1024) kAll(
    const float* __restrict__ w0, const float* __restrict__ b0,
    const float* __restrict__ w1, const float* __restrict__ b1,
    const float* __restrict__ w2, const float* __restrict__ b2,
    const BParam Bp,
    const float* __restrict__ w3, const float* __restrict__ b3, int nrows)
{
    extern __shared__ char smem_raw[];
    SmemAll& sm = *reinterpret_cast<SmemAll*>(smem_raw);

    const int grp = blockIdx.x;
    const int i0 = grp * 32;
    const int tid = threadIdx.x;

    // ---- S0: u,c fold (j = tid&255 column, q = tid>>8 k-chunk of 64) ----
    {
        const int j = tid & 255;
        const int q = tid >> 8;
        float uu = 0.f, cc = 0.f;
#pragma unroll 8
        for (int kk = 0; kk < 64; kk++) {
            int k = q * 64 + kk;
            float wv = w1[k * HDIM + j];
            uu = fmaf(w0[k], wv, uu);
            cc = fmaf(b0[k], wv, cc);
        }
        sm.u.s0.up[q][j] = uu;
        sm.u.s0.cp[q][j] = cc;
    }
    if (tid < 32)
        sm.xs[tid] = (float)(i0 + tid) * (1.0f / (float)GTAB);
    __syncthreads();
    if (tid < HDIM) {
        float uu = sm.u.s0.up[0][tid] + sm.u.s0.up[1][tid]
                 + sm.u.s0.up[2][tid] + sm.u.s0.up[3][tid];
        float cc = sm.u.s0.cp[0][tid] + sm.u.s0.cp[1][tid]
                 + sm.u.s0.cp[2][tid] + sm.u.s0.cp[3][tid];
        sm.us[tid] = uu;
        sm.cs[tid] = cc + b1[tid];
    }
    __syncthreads();

    // ---- S1: H2 GEMM, 32x256 tile, BK=16, 4x2 microtile ----
    const int tx = tid & 127;      // 128 col groups of 2
    const int ty = tid >> 7;       // 8 row groups of 4

    float acc[4][2];
#pragma unroll
    for (int m = 0; m < 4; m++) { acc[m][0] = 0.f; acc[m][1] = 0.f; }

    for (int k0 = 0; k0 < HDIM; k0 += 16) {
        if (tid < 512) {                        // As: 512 elems
            int kk = tid >> 5, ii = tid & 31;
            sm.u.s1.As[kk][ii] =
                fmaxf(fmaf(sm.xs[ii], sm.us[k0 + kk], sm.cs[k0 + kk]), 0.f);
        }
#pragma unroll
        for (int s = 0; s < 4; s++) {           // Bs: 4096 elems
            int e = tid + s * 1024;
            int kk = e >> 8, jj = e & 255;
            sm.u.s1.Bs[kk][jj] = w2[(k0 + kk) * HDIM + jj];
        }
        __syncthreads();
#pragma unroll
        for (int kk = 0; kk < 16; kk++) {
            float4 a4 = *reinterpret_cast<const float4*>(&sm.u.s1.As[kk][ty * 4]);
            float2 bv = *reinterpret_cast<const float2*>(&sm.u.s1.Bs[kk][tx * 2]);
            float a[4] = {a4.x, a4.y, a4.z, a4.w};
#pragma unroll
            for (int m = 0; m < 4; m++) {
                acc[m][0] = fmaf(a[m], bv.x, acc[m][0]);
                acc[m][1] = fmaf(a[m], bv.y, acc[m][1]);
            }
        }
        __syncthreads();
    }

    // ---- S2: H2 tile -> smem (relu + b2) ----
    {
        float bb0 = b2[tx * 2];
        float bb1 = b2[tx * 2 + 1];
#pragma unroll
        for (int m = 0; m < 4; m++) {
            float2 v;
            v.x = fmaxf(acc[m][0] + bb0, 0.f);
            v.y = fmaxf(acc[m][1] + bb1, 0.f);
            *reinterpret_cast<float2*>(&sm.H2t[ty * 4 + m][tx * 2]) = v;
        }
    }
    __syncthreads();

    // ---- S3: T = H2 @ w3 + b3  (thread per (i,d); broadcast smem reads) ----
    {
        const int i = tid >> 5;      // 0..31
        const int d = tid & 31;      // 0..31 (31 invalid)
        if (d < DTH) {
            float a = 0.f;
#pragma unroll 8
            for (int jj = 0; jj < 256; jj++)
                a = fmaf(sm.H2t[i][jj], __ldg(&w3[jj * DTH + d]), a);
            sm.u.s34.Ts[d][i] = a + b3[d];
        }
    }
    // stage the basis while S3 finishes elsewhere
    for (int e = tid; e < DTH * 64; e += 1024)
        sm.u.s34.Bb[e >> 6][e & 63] = Bp.B[e];
    __syncthreads();

    // ---- S4: A = T @ B^T -> g_Atab (2 rows per thread) ----
    {
        const int j = tid & 63;
        const int ig = tid >> 6;     // 0..15; rows ig and ig+16
        float a0 = 0.f, a1 = 0.f;
#pragma unroll
        for (int d = 0; d < DTH; d++) {
            float bv = sm.u.s34.Bb[d][j];
            a0 = fmaf(sm.u.s34.Ts[d][ig], bv, a0);
            a1 = fmaf(sm.u.s34.Ts[d][ig + 16], bv, a1);
        }
        int r0 = i0 + ig, r1 = i0 + ig + 16;
        if (r0 < nrows) g_Atab[r0 * 64 + j] = a0;
        if (r1 < nrows) g_Atab[r1 * 64 + j] = a1;
    }
}

// ============================================================================
// k3: CPAB integration, 1 point/thread, fast intrinsics throughout
//     (incl. e=b/a — table error dominates budget ~150x). Exact fixpoint
//     early-exit; redundant clamps removed.
// ============================================================================
__global__ void __launch_bounds__(256) k3_integrate(const float* __restrict__ x,
                                                    float* __restrict__ out, int n)
{
    const int ip = blockIdx.x * 256 + threadIdx.x;
    if (ip >= n) return;

    float2 xv = *reinterpret_cast<const float2*>(&x[2 * ip]);
    float x1 = fminf(fmaxf(xv.y, EPSF), 1.0f - EPSF);
    float f = x1 * (float)GTAB;
    int r = (int)f;                                  // in [0, GTAB-1] by range
    float fr = f - (float)r;
    const float2* row0 = reinterpret_cast<const float2*>(&g_Atab[r * 64]);
    const float2* row1 = reinterpret_cast<const float2*>(&g_Atab[(r + 1) * 64]);

    float xc = fminf(fmaxf(xv.x, EPSF), 1.0f - EPSF);
    float t = 1.0f;
    float S = 0.0f;
    const float inv = 1.0f / (float)NCELL;
    const float INF = __int_as_float(0x7f800000);

#pragma unroll 1
    for (int it = 0; it < NCELL + 2; it++) {
        int c = (int)(xc * (float)NCELL);            // in [0, 31] by range
        float2 p0 = __ldg(&row0[c]);
        float2 p1 = __ldg(&row1[c]);
        float a = fmaf(fr, p1.x - p0.x, p0.x);
        float b = fmaf(fr, p1.y - p0.y, p0.y);
        float v = a * xc + b;
        float xbnd = ((v >= 0.f) ? (float)(c + 1) : (float)c) * inv;
        bool  small_a = fabsf(a) < TINYF;
        float safe_a = small_a ? 1.0f : a;
        float e = __fdividef(b, safe_a);
        float denom = xc + e;
        float safe_denom = (fabsf(denom) < TINYF) ? ((denom >= 0.f) ? TINYF : -TINYF) : denom;
        float ratio = __fdividef(xbnd + e, safe_denom);
        float thit_exp = __fdividef(__logf(fmaxf(ratio, TINYF)), safe_a);
        float safe_b = (fabsf(b) < TINYF) ? TINYF : b;
        float thit_lin = __fdividef(xbnd - xc, safe_b);
        float thit = small_a ? thit_lin : ((ratio > TINYF) ? thit_exp : INF);
        thit = (thit <= 0.f) ? INF : thit;
        float dt = fminf(thit, t);
        bool cross = (thit <= t);
        float x_exp = (xc + e) * __expf(a * dt) - e;
        float x_lin = xc + b * dt;
        float xn = small_a ? x_lin : x_exp;
        float nudge = (v >= 0.f) ? 1e-7f : -1e-7f;
        xn = cross ? (xbnd + nudge) : xn;
        xn = fminf(fmaxf(xn, EPSF), 1.0f - EPSF);
        S += a * dt;
        t = t - dt;
        bool done = (dt == 0.0f) && (xn == xc);     // exact fixpoint
        xc = xn;
        if (__all_sync(0xffffffffu, done)) break;
    }

    float2 z; z.x = xc; z.y = x1;
    *reinterpret_cast<float2*>(&out[2 * ip]) = z;
    float2 g; g.x = S; g.y = 0.0f;
    *reinterpret_cast<float2*>(&out[2 * n + 2 * ip]) = g;
}

// ============================================================================
static BParam s_Bp;               // persists across graph replays

extern "C" void kernel_launch(void* const* d_in, const int* in_sizes, int n_in,
                              void* d_out, int out_size)
{
    const float* x  = (const float*)d_in[0];
    const float* w0 = (const float*)d_in[1];
    const float* b0 = (const float*)d_in[2];
    const float* w1 = (const float*)d_in[3];
    const float* b1 = (const float*)d_in[4];
    const float* w2 = (const float*)d_in[5];
    const float* b2 = (const float*)d_in[6];
    const float* w3 = (const float*)d_in[7];
    const float* b3 = (const float*)d_in[8];
    float* out = (float*)d_out;

    int n = in_sizes[0] / 2;
    const int nrows = GTAB + 1;
    const int smem_bytes = (int)sizeof(SmemAll);

    compute_basis_host(s_Bp.B);     // input-independent, deterministic
    cudaFuncSetAttribute(kAll, cudaFuncAttributeMaxDynamicSharedMemorySize,
                         smem_bytes);

    kAll<<<NGRP, 1024, smem_bytes>>>(w0, b0, w1, b1, w2, b2, s_Bp, w3, b3, nrows);

    k3_integrate<<<(n + 255) / 256, 256>>>(x, out, n);
}

// round 17
// speedup vs baseline: 1.5474x; 1.5474x over previous
#include <cuda_runtime.h>
#include <math.h>
#include <string.h>

#define HDIM   256
#define NCELL  32
#define DTH    31
#define EPSF   1e-7f
#define TINYF  1e-10f
#define GTAB   512                   // table cells; nodes = GTAB+1
#define KCH    32                    // k-chunks for u,c partial reduction
#define NGRP   17                    // row groups of 32 (covers GTAB+1 rows)

// ---------------- device scratch (no cudaMalloc allowed) ----------------
__device__ float g_upart[KCH * HDIM];          // partial sums of u
__device__ float g_cpart[KCH * HDIM];          // partial sums of c (pre-b1)
__device__ float g_Tpart[NGRP * 4 * 32 * DTH]; // per-(grp,jy) w3 projections
__device__ float g_AtabI[(GTAB + 2) * 128];    // interleaved (a,b,da,db), 4 fl/cell

struct BParam { float B[DTH * 64]; };          // 7936 B kernel param

// ============================================================================
// Host: numpy SVD null-space basis B = Vt[33:].T via Householder LQ
// (dgesdd Path 4t: dgelqf + dorglq). Input-independent -> host fp64.
// ============================================================================
static void compute_basis_host(float* Bout /* [DTH][64] */)
{
    static double L[33][64];
    static double Bm[DTH][64];
    static double tau[33];
    memset(L, 0, sizeof(L));
    memset(Bm, 0, sizeof(Bm));

    for (int i = 1; i < NCELL; i++) {
        double xi = (double)i / (double)NCELL;
        L[i - 1][2 * (i - 1)]     = xi;
        L[i - 1][2 * (i - 1) + 1] = 1.0;
        L[i - 1][2 * i]           = -xi;
        L[i - 1][2 * i + 1]       = -1.0;
    }
    L[NCELL - 1][1]               = 1.0;
    L[NCELL][2 * (NCELL - 1)]     = 1.0;
    L[NCELL][2 * (NCELL - 1) + 1] = 1.0;

    for (int i = 0; i < 33; i++) {
        double xn2 = 0.0;
        for (int j = i + 1; j < 64; j++) xn2 += L[i][j] * L[i][j];
        if (xn2 == 0.0) { tau[i] = 0.0; continue; }
        double alpha = L[i][i];
        double beta = sqrt(alpha * alpha + xn2);
        beta = (alpha >= 0.0) ? -beta : beta;
        tau[i] = (beta - alpha) / beta;
        double sc = 1.0 / (alpha - beta);
        for (int j = i + 1; j < 64; j++) L[i][j] *= sc;
        L[i][i] = beta;
        for (int r = i + 1; r < 33; r++) {
            double w = L[r][i];
            for (int j = i + 1; j < 64; j++) w += L[r][j] * L[i][j];
            w *= tau[i];
            L[r][i] -= w;
            for (int j = i + 1; j < 64; j++) L[r][j] -= w * L[i][j];
        }
    }
    for (int r = 0; r < DTH; r++) Bm[r][33 + r] = 1.0;
    for (int i = 32; i >= 0; i--) {
        if (tau[i] == 0.0) continue;
        for (int r = 0; r < DTH; r++) {
            double w = Bm[r][i];
            for (int j = i + 1; j < 64; j++) w += Bm[r][j] * L[i][j];
            w *= tau[i];
            Bm[r][i] -= w;
            for (int j = i + 1; j < 64; j++) Bm[r][j] -= w * L[i][j];
        }
    }
    for (int d = 0; d < DTH; d++)
        for (int j = 0; j < 64; j++)
            Bout[d * 64 + j] = (float)Bm[d][j];
}

// ============================================================================
// k0u: stage-1 partial reduction of u = w0@w1, c = b0@w1.
// ============================================================================
__global__ void __launch_bounds__(128) k0u_part(
    const float* __restrict__ w0, const float* __restrict__ b0,
    const float* __restrict__ w1)
{
    const int j = blockIdx.y * 128 + threadIdx.x;
    const int b = blockIdx.x;
    float uu = 0.f, cc = 0.f;
#pragma unroll
    for (int kk = 0; kk < HDIM / KCH; kk++) {
        int k = b * (HDIM / KCH) + kk;
        float wv = w1[k * HDIM + j];
        uu = fmaf(w0[k], wv, uu);
        cc = fmaf(b0[k], wv, cc);
    }
    g_upart[b * HDIM + j] = uu;
    g_cpart[b * HDIM + j] = cc;
}

// ============================================================================
// kT1: h2 tile (32 rows x 64 cols) + immediate w3 projection -> g_Tpart.
//      (R14 structure: proven config.)
// ============================================================================
__global__ void __launch_bounds__(256) kT1_h2proj(
    const float* __restrict__ b1,
    const float* __restrict__ w2, const float* __restrict__ b2,
    const float* __restrict__ w3)
{
    __shared__ float us[HDIM], cs[HDIM];
    __shared__ float xs[32];
    __shared__ float As[16][36];     // stride 144B (16B-aligned)
    __shared__ float Bs[16][64];
    __shared__ float H2t[32][66];    // stride 264B (8B-aligned for float2)

    const int grp = blockIdx.x;
    const int jy  = blockIdx.y;
    const int i0 = grp * 32;
    const int j0 = jy * 64;
    const int tid = threadIdx.x;

    {
        float uu = 0.f, cc = 0.f;
#pragma unroll
        for (int b = 0; b < KCH; b++) {
            uu += g_upart[b * HDIM + tid];
            cc += g_cpart[b * HDIM + tid];
        }
        us[tid] = uu;
        cs[tid] = cc + b1[tid];
    }
    if (tid < 32)
        xs[tid] = (float)(i0 + tid) * (1.0f / (float)GTAB);
    __syncthreads();

    const int tx = tid & 31;       // 32 col groups of 2
    const int ty = tid >> 5;       // 8 row groups of 4

    float acc[4][2];
#pragma unroll
    for (int m = 0; m < 4; m++) { acc[m][0] = 0.f; acc[m][1] = 0.f; }

    for (int k0 = 0; k0 < HDIM; k0 += 16) {
#pragma unroll
        for (int s = 0; s < 2; s++) {           // As: 512 elems
            int e = tid + s * 256;
            int kk = e >> 5, ii = e & 31;
            As[kk][ii] = fmaxf(fmaf(xs[ii], us[k0 + kk], cs[k0 + kk]), 0.f);
        }
#pragma unroll
        for (int s = 0; s < 4; s++) {           // Bs: 1024 elems
            int e = tid + s * 256;
            int kk = e >> 6, jj = e & 63;
            Bs[kk][jj] = w2[(k0 + kk) * HDIM + j0 + jj];
        }
        __syncthreads();
#pragma unroll
        for (int kk = 0; kk < 16; kk++) {
            float4 a4 = *reinterpret_cast<const float4*>(&As[kk][ty * 4]);
            float2 bv = *reinterpret_cast<const float2*>(&Bs[kk][tx * 2]);
            float a[4] = {a4.x, a4.y, a4.z, a4.w};
#pragma unroll
            for (int m = 0; m < 4; m++) {
                acc[m][0] = fmaf(a[m], bv.x, acc[m][0]);
                acc[m][1] = fmaf(a[m], bv.y, acc[m][1]);
            }
        }
        __syncthreads();
    }

    float bb0 = b2[j0 + tx * 2];
    float bb1 = b2[j0 + tx * 2 + 1];
#pragma unroll
    for (int m = 0; m < 4; m++) {
        float2 v;
        v.x = fmaxf(acc[m][0] + bb0, 0.f);
        v.y = fmaxf(acc[m][1] + bb1, 0.f);
        *reinterpret_cast<float2*>(&H2t[ty * 4 + m][tx * 2]) = v;
    }
    __syncthreads();

    // Tpart[i][d] = sum_jj H2t[i][jj] * w3[(j0+jj)*DTH + d]
    {
        const int i = tid & 31;
        const int dg = tid >> 5;             // 8 groups x 4 d
        const int d0 = dg * 4;
        float a4[4] = {0.f, 0.f, 0.f, 0.f};
#pragma unroll 8
        for (int jj = 0; jj < 64; jj++) {
            float h = H2t[i][jj];
            const float* w3r = &w3[(j0 + jj) * DTH + d0];
            a4[0] = fmaf(h, __ldg(&w3r[0]), a4[0]);
            if (d0 + 1 < DTH) a4[1] = fmaf(h, __ldg(&w3r[1]), a4[1]);
            if (d0 + 2 < DTH) a4[2] = fmaf(h, __ldg(&w3r[2]), a4[2]);
            if (d0 + 3 < DTH) a4[3] = fmaf(h, __ldg(&w3r[3]), a4[3]);
        }
        float* tp = &g_Tpart[((grp * 4 + jy) * 32 + i) * DTH + d0];
        tp[0] = a4[0];
        if (d0 + 1 < DTH) tp[1] = a4[1];
        if (d0 + 2 < DTH) tp[2] = a4[2];
        if (d0 + 3 < DTH) tp[3] = a4[3];
    }
}

// ============================================================================
// kT2: reducer + interleaved table emit.
//      T = sum_jy Tpart (+b3) for 33 rows (row 32 = next group's row 0,
//      same data + same fixed-order sum -> bit-identical to neighbor's own);
//      A = T @ B^T  (33 rows in smem);
//      emit per (row, cell): float4 (a, b, a_next-a, b_next-b) at
//      g_AtabI[row*128 + c*4].  Only rows < GTAB are ever dereferenced.
// ============================================================================
__global__ void __launch_bounds__(256) kT2_atab(
    const BParam Bp, const float* __restrict__ b3)
{
    __shared__ float Ts[32][34];     // [d][i], i in 0..32
    __shared__ float Bb[DTH][64];
    __shared__ float Asm[33][66];    // A rows [i][j], j in 0..63

    const int grp = blockIdx.x;
    const int i0 = grp * 32;
    const int tid = threadIdx.x;

    // sum 4 parts in fixed order (deterministic), 33 rows
    for (int e = tid; e < 33 * DTH; e += 256) {
        int i = e / DTH, d = e % DTH;
        float s = 0.f;
        if (i < 32) {
            const float* tp = &g_Tpart[((grp * 4) * 32 + i) * DTH + d];
            s = tp[0] + tp[32 * DTH] + tp[2 * 32 * DTH] + tp[3 * 32 * DTH];
        } else if (grp + 1 < NGRP) {
            const float* tp = &g_Tpart[(((grp + 1) * 4) * 32 + 0) * DTH + d];
            s = tp[0] + tp[32 * DTH] + tp[2 * 32 * DTH] + tp[3 * 32 * DTH];
        }
        Ts[d][i] = s + b3[d];
    }
    for (int e = tid; e < DTH * 64; e += 256)
        Bb[e >> 6][e & 63] = Bp.B[e];
    __syncthreads();

    // A = T @ B^T  (33 rows)
    {
        const int j = tid & 63;
        const int ig = tid >> 6;             // 0..3
#pragma unroll
        for (int m = 0; m < 9; m++) {
            int i = ig + m * 4;
            if (i < 33) {
                float a = 0.f;
#pragma unroll
                for (int d = 0; d < DTH; d++)
                    a = fmaf(Ts[d][i], Bb[d][j], a);
                Asm[i][j] = a;
            }
        }
    }
    __syncthreads();

    // emit: 32 rows x 32 cells, one float4 each
    for (int e = tid; e < 32 * 32; e += 256) {
        int i = e >> 5, c = e & 31;
        int row = i0 + i;
        if (row < GTAB) {                    // rows >= GTAB never dereferenced
            float a0 = Asm[i][2 * c];
            float b0v = Asm[i][2 * c + 1];
            float a1 = Asm[i + 1][2 * c];
            float b1v = Asm[i + 1][2 * c + 1];
            float4 q;
            q.x = a0; q.y = b0v;
            q.z = a1 - a0; q.w = b1v - b0v;
            *reinterpret_cast<float4*>(&g_AtabI[row * 128 + c * 4]) = q;
        }
    }
}

// ============================================================================
// k3: CPAB integration, 1 point/thread. Interleaved table: ONE float4 load
//     per iteration gives (a,b,da,db); lerp bit-identical to two-row form.
//     Fast intrinsics throughout; exact fixpoint early-exit.
// ============================================================================
__global__ void __launch_bounds__(256) k3_integrate(const float* __restrict__ x,
                                                    float* __restrict__ out, int n)
{
    const int ip = blockIdx.x * 256 + threadIdx.x;
    if (ip >= n) return;

    float2 xv = *reinterpret_cast<const float2*>(&x[2 * ip]);
    float x1 = fminf(fmaxf(xv.y, EPSF), 1.0f - EPSF);
    float f = x1 * (float)GTAB;
    int r = (int)f;                                  // in [0, GTAB-1] by range
    float fr = f - (float)r;
    const float4* tab = reinterpret_cast<const float4*>(&g_AtabI[r * 128]);

    float xc = fminf(fmaxf(xv.x, EPSF), 1.0f - EPSF);
    float t = 1.0f;
    float S = 0.0f;
    const float inv = 1.0f / (float)NCELL;
    const float INF = __int_as_float(0x7f800000);

#pragma unroll 1
    for (int it = 0; it < NCELL + 2; it++) {
        int c = (int)(xc * (float)NCELL);            // in [0, 31] by range
        float4 q = __ldg(&tab[c]);                   // (a, b, da, db) for cell c
        float a = fmaf(fr, q.z, q.x);
        float b = fmaf(fr, q.w, q.y);
        float v = a * xc + b;
        float xbnd = ((v >= 0.f) ? (float)(c + 1) : (float)c) * inv;
        bool  small_a = fabsf(a) < TINYF;
        float safe_a = small_a ? 1.0f : a;
        float e = __fdividef(b, safe_a);
        float denom = xc + e;
        float safe_denom = (fabsf(denom) < TINYF) ? ((denom >= 0.f) ? TINYF : -TINYF) : denom;
        float ratio = __fdividef(xbnd + e, safe_denom);
        float thit_exp = __fdividef(__logf(fmaxf(ratio, TINYF)), safe_a);
        float safe_b = (fabsf(b) < TINYF) ? TINYF : b;
        float thit_lin = __fdividef(xbnd - xc, safe_b);
        float thit = small_a ? thit_lin : ((ratio > TINYF) ? thit_exp : INF);
        thit = (thit <= 0.f) ? INF : thit;
        float dt = fminf(thit, t);
        bool cross = (thit <= t);
        float x_exp = (xc + e) * __expf(a * dt) - e;
        float x_lin = xc + b * dt;
        float xn = small_a ? x_lin : x_exp;
        float nudge = (v >= 0.f) ? 1e-7f : -1e-7f;
        xn = cross ? (xbnd + nudge) : xn;
        xn = fminf(fmaxf(xn, EPSF), 1.0f - EPSF);
        S += a * dt;
        t = t - dt;
        bool done = (dt == 0.0f) && (xn == xc);     // exact fixpoint
        xc = xn;
        if (__all_sync(0xffffffffu, done)) break;
    }

    float2 z; z.x = xc; z.y = x1;
    *reinterpret_cast<float2*>(&out[2 * ip]) = z;
    float2 g; g.x = S; g.y = 0.0f;
    *reinterpret_cast<float2*>(&out[2 * n + 2 * ip]) = g;
}

// ============================================================================
static BParam s_Bp;               // persists across graph replays

extern "C" void kernel_launch(void* const* d_in, const int* in_sizes, int n_in,
                              void* d_out, int out_size)
{
    const float* x  = (const float*)d_in[0];
    const float* w0 = (const float*)d_in[1];
    const float* b0 = (const float*)d_in[2];
    const float* w1 = (const float*)d_in[3];
    const float* b1 = (const float*)d_in[4];
    const float* w2 = (const float*)d_in[5];
    const float* b2 = (const float*)d_in[6];
    const float* w3 = (const float*)d_in[7];
    const float* b3 = (const float*)d_in[8];
    float* out = (float*)d_out;

    int n = in_sizes[0] / 2;

    compute_basis_host(s_Bp.B);     // input-independent, deterministic

    dim3 g0(KCH, 2);
    k0u_part<<<g0, 128>>>(w0, b0, w1);

    dim3 g1(NGRP, 4);
    kT1_h2proj<<<g1, 256>>>(b1, w2, b2, w3);

    kT2_atab<<<NGRP, 256>>>(s_Bp, b3);

    k3_integrate<<<(n + 255) / 256, 256>>>(x, out, n);
}